// round 15
// baseline (speedup 1.0000x reference)
#include <cuda_runtime.h>
#include <math.h>

#define N_SPANS 4096
#define EMB     384
#define HEADS   4
#define NH      (HEADS * EMB)   // 1536
#define BAND    11              // exp(-12/5) < 0.1, so |i-j| <= 11
#define BW      (2 * BAND + 1)  // 23

// ---------------- scratch (static device globals; no allocations) -----------
__device__ float    g_en[N_SPANS * EMB];     // normalized embeddings
__device__ float    g_x[N_SPANS * NH];       // projected features [N, H, E]
__device__ float    g_asrc[N_SPANS * HEADS];
__device__ float    g_adst[N_SPANS * HEADS];
__device__ unsigned g_mask[N_SPANS];         // 23-bit band mask per dst row

// ---------------- 1) row-normalize embeddings --------------------------------
__global__ void k_norm(const float* __restrict__ E) {
    int i = blockIdx.x;
    __shared__ float red[4];
    float s = 0.f;
    for (int e = threadIdx.x; e < EMB; e += 128) {
        float v = E[i * EMB + e];
        s += v * v;
    }
    #pragma unroll
    for (int o = 16; o > 0; o >>= 1) s += __shfl_down_sync(0xffffffffu, s, o);
    if ((threadIdx.x & 31) == 0) red[threadIdx.x >> 5] = s;
    __syncthreads();
    if (threadIdx.x == 0) red[0] = rsqrtf(red[0] + red[1] + red[2] + red[3]);
    __syncthreads();
    float inv = red[0];
    for (int e = threadIdx.x; e < EMB; e += 128)
        g_en[i * EMB + e] = E[i * EMB + e] * inv;
}

// ---------------- 2) banded adjacency mask -----------------------------------
__global__ void k_mask() {
    int i = blockIdx.x;
    int w = threadIdx.x >> 5, lane = threadIdx.x & 31;  // 8 warps
    __shared__ unsigned sm;
    if (threadIdx.x == 0) sm = 0u;
    __syncthreads();
    for (int d = w; d < BW; d += 8) {
        int j = i - BAND + d;
        if (j < 0 || j >= N_SPANS) continue;
        float s = 0.f;
        const float* ei = g_en + (size_t)i * EMB;
        const float* ej = g_en + (size_t)j * EMB;
        for (int e = lane; e < EMB; e += 32) s += ei[e] * ej[e];
        #pragma unroll
        for (int o = 16; o > 0; o >>= 1) s += __shfl_down_sync(0xffffffffu, s, o);
        if (lane == 0) {
            float adj = s * expf(-fabsf((float)(i - j)) * 0.2f);
            if (adj > 0.1f) atomicOr(&sm, 1u << d);
        }
    }
    __syncthreads();
    if (threadIdx.x == 0) g_mask[i] = sm;
}

// ---------------- 3) projection GEMM: x[4096,1536] = E[4096,384] @ W[384,1536]
#define BM 64
#define BN 64
#define BK 16

__global__ __launch_bounds__(256) void k_gemm(const float* __restrict__ A,
                                              const float* __restrict__ B) {
    __shared__ float As[BK][BM + 4];  // transposed A tile, padded
    __shared__ float Bs[BK][BN];
    int tid = threadIdx.x;
    int tx = tid & 15, ty = tid >> 4;
    int m0 = blockIdx.y * BM, n0 = blockIdx.x * BN;

    int ar = tid >> 2, av = tid & 3;   // A loader: row 0..63, float4 0..3
    int br = tid >> 4, bv = tid & 15;  // B loader: row 0..15, float4 0..15

    const float* Aptr = A + (size_t)(m0 + ar) * EMB + av * 4;
    const float* Bptr = B + (size_t)br * NH + n0 + bv * 4;

    float acc[4][4] = {};

    for (int kt = 0; kt < EMB; kt += BK) {
        float4 a4 = *(const float4*)(Aptr + kt);
        As[av * 4 + 0][ar] = a4.x;
        As[av * 4 + 1][ar] = a4.y;
        As[av * 4 + 2][ar] = a4.z;
        As[av * 4 + 3][ar] = a4.w;
        *(float4*)(&Bs[br][bv * 4]) = *(const float4*)(Bptr + (size_t)kt * NH);
        __syncthreads();
        #pragma unroll
        for (int k = 0; k < BK; k++) {
            float4 a = *(const float4*)(&As[k][ty * 4]);
            float4 b = *(const float4*)(&Bs[k][tx * 4]);
            acc[0][0] += a.x * b.x; acc[0][1] += a.x * b.y; acc[0][2] += a.x * b.z; acc[0][3] += a.x * b.w;
            acc[1][0] += a.y * b.x; acc[1][1] += a.y * b.y; acc[1][2] += a.y * b.z; acc[1][3] += a.y * b.w;
            acc[2][0] += a.z * b.x; acc[2][1] += a.z * b.y; acc[2][2] += a.z * b.z; acc[2][3] += a.z * b.w;
            acc[3][0] += a.w * b.x; acc[3][1] += a.w * b.y; acc[3][2] += a.w * b.z; acc[3][3] += a.w * b.w;
        }
        __syncthreads();
    }

    float* X = g_x + (size_t)(m0 + ty * 4) * NH + n0 + tx * 4;
    #pragma unroll
    for (int r = 0; r < 4; r++) {
        float4 o = make_float4(acc[r][0], acc[r][1], acc[r][2], acc[r][3]);
        *(float4*)(X + (size_t)r * NH) = o;
    }
}

// ---------------- 4) per-node attention scalars ------------------------------
__global__ void k_attvec(const float* __restrict__ att_src,
                         const float* __restrict__ att_dst) {
    int n = blockIdx.x;
    int h = threadIdx.x >> 5, lane = threadIdx.x & 31;  // 4 warps, one per head
    const float* xr = g_x + (size_t)n * NH + h * EMB;
    const float* as = att_src + h * EMB;
    const float* ad = att_dst + h * EMB;
    float s1 = 0.f, s2 = 0.f;
    for (int e = lane; e < EMB; e += 32) {
        float v = xr[e];
        s1 += v * as[e];
        s2 += v * ad[e];
    }
    #pragma unroll
    for (int o = 16; o > 0; o >>= 1) {
        s1 += __shfl_down_sync(0xffffffffu, s1, o);
        s2 += __shfl_down_sync(0xffffffffu, s2, o);
    }
    if (lane == 0) {
        g_asrc[n * HEADS + h] = s1;
        g_adst[n * HEADS + h] = s2;
    }
}

// ---------------- 5) band softmax + weighted aggregation ---------------------
__global__ void k_attn(const float* __restrict__ bias, float* __restrict__ out) {
    int i = blockIdx.x;
    __shared__ float alpha[HEADS][BW + 1];  // logits first, then alphas
    unsigned m = g_mask[i];
    int t = threadIdx.x;

    if (t < HEADS * BW) {
        int h = t / BW, d = t % BW;
        int j = i - BAND + d;
        float l = -INFINITY;
        if (j >= 0 && j < N_SPANS && ((m >> d) & 1u)) {
            float v = g_adst[i * HEADS + h] + g_asrc[j * HEADS + h];
            l = (v >= 0.f) ? v : 0.2f * v;
        }
        alpha[h][d] = l;
    }
    __syncthreads();

    if (t < HEADS) {
        float mx = -INFINITY;
        #pragma unroll
        for (int d = 0; d < BW; d++) mx = fmaxf(mx, alpha[t][d]);
        float ex[BW];
        float s = 0.f;
        #pragma unroll
        for (int d = 0; d < BW; d++) { float e = expf(alpha[t][d] - mx); ex[d] = e; s += e; }
        float inv = 1.f / s;
        #pragma unroll
        for (int d = 0; d < BW; d++) alpha[t][d] = ex[d] * inv;
    }
    __syncthreads();

    int jlo = (i - BAND < 0) ? 0 : i - BAND;
    int jhi = (i + BAND >= N_SPANS) ? N_SPANS - 1 : i + BAND;

    for (int e = t; e < EMB; e += 128) {
        float acc = 0.f;
        for (int j = jlo; j <= jhi; j++) {
            int d = j - (i - BAND);
            const float* xr = g_x + (size_t)j * NH + e;
            acc += alpha[0][d] * xr[0]
                 + alpha[1][d] * xr[EMB]
                 + alpha[2][d] * xr[2 * EMB]
                 + alpha[3][d] * xr[3 * EMB];
        }
        out[i * EMB + e] = acc * 0.25f + bias[e];
    }
}

// -----------------------------------------------------------------------------
extern "C" void kernel_launch(void* const* d_in, const int* in_sizes, int n_in,
                              void* d_out, int out_size) {
    const float* E    = (const float*)d_in[0];
    // d_in[1] = span_positions (int64) — unused by the reference
    const float* W    = (const float*)d_in[2];   // [384, 4, 384] == [384, 1536] row-major
    const float* asv  = (const float*)d_in[3];   // att_src [4, 384]
    const float* adv  = (const float*)d_in[4];   // att_dst [4, 384]
    const float* bias = (const float*)d_in[5];   // [384]
    float* out = (float*)d_out;                  // [4096, 384] fp32

    k_norm<<<N_SPANS, 128>>>(E);
    k_mask<<<N_SPANS, 256>>>();
    k_gemm<<<dim3(NH / BN, N_SPANS / BM), 256>>>(E, W);
    k_attvec<<<N_SPANS, 128>>>(asv, adv);
    k_attn<<<N_SPANS, 128>>>(bias, out);
}

// round 16
// speedup vs baseline: 1.0080x; 1.0080x over previous
#include <cuda_runtime.h>
#include <math.h>

#define N_SPANS 4096
#define EMB     384
#define HEADS   4
#define NH      (HEADS * EMB)   // 1536
#define BAND    11              // exp(-12/5) < 0.1, so |i-j| <= 11
#define BW      (2 * BAND + 1)  // 23

// ---------------- scratch (static device globals; no allocations) -----------
__device__ float    g_en[N_SPANS * EMB];     // normalized embeddings
__device__ float    g_x[N_SPANS * NH];       // projected features [N, H, E]
__device__ float    g_asrc[N_SPANS * HEADS];
__device__ float    g_adst[N_SPANS * HEADS];
__device__ unsigned g_mask[N_SPANS];         // 23-bit band mask per dst row

// ---------------- 1) row-normalize embeddings --------------------------------
__global__ void k_norm(const float* __restrict__ E) {
    int i = blockIdx.x;
    __shared__ float red[4];
    float s = 0.f;
    for (int e = threadIdx.x; e < EMB; e += 128) {
        float v = E[i * EMB + e];
        s += v * v;
    }
    #pragma unroll
    for (int o = 16; o > 0; o >>= 1) s += __shfl_down_sync(0xffffffffu, s, o);
    if ((threadIdx.x & 31) == 0) red[threadIdx.x >> 5] = s;
    __syncthreads();
    if (threadIdx.x == 0) red[0] = rsqrtf(red[0] + red[1] + red[2] + red[3]);
    __syncthreads();
    float inv = red[0];
    for (int e = threadIdx.x; e < EMB; e += 128)
        g_en[i * EMB + e] = E[i * EMB + e] * inv;
}

// ---------------- 2) banded adjacency mask -----------------------------------
__global__ void k_mask() {
    int i = blockIdx.x;
    int w = threadIdx.x >> 5, lane = threadIdx.x & 31;  // 8 warps
    __shared__ unsigned sm;
    if (threadIdx.x == 0) sm = 0u;
    __syncthreads();
    for (int d = w; d < BW; d += 8) {
        int j = i - BAND + d;
        if (j < 0 || j >= N_SPANS) continue;
        float s = 0.f;
        const float* ei = g_en + (size_t)i * EMB;
        const float* ej = g_en + (size_t)j * EMB;
        for (int e = lane; e < EMB; e += 32) s += ei[e] * ej[e];
        #pragma unroll
        for (int o = 16; o > 0; o >>= 1) s += __shfl_down_sync(0xffffffffu, s, o);
        if (lane == 0) {
            float adj = s * expf(-fabsf((float)(i - j)) * 0.2f);
            if (adj > 0.1f) atomicOr(&sm, 1u << d);
        }
    }
    __syncthreads();
    if (threadIdx.x == 0) g_mask[i] = sm;
}

// ---------------- 3) projection GEMM: x[4096,1536] = E[4096,384] @ W[384,1536]
#define BM 64
#define BN 64
#define BK 16

__global__ __launch_bounds__(256) void k_gemm(const float* __restrict__ A,
                                              const float* __restrict__ B) {
    __shared__ float As[BK][BM + 4];  // transposed A tile, padded
    __shared__ float Bs[BK][BN];
    int tid = threadIdx.x;
    int tx = tid & 15, ty = tid >> 4;
    int m0 = blockIdx.y * BM, n0 = blockIdx.x * BN;

    int ar = tid >> 2, av = tid & 3;   // A loader: row 0..63, float4 0..3
    int br = tid >> 4, bv = tid & 15;  // B loader: row 0..15, float4 0..15

    const float* Aptr = A + (size_t)(m0 + ar) * EMB + av * 4;
    const float* Bptr = B + (size_t)br * NH + n0 + bv * 4;

    float acc[4][4] = {};

    for (int kt = 0; kt < EMB; kt += BK) {
        float4 a4 = *(const float4*)(Aptr + kt);
        As[av * 4 + 0][ar] = a4.x;
        As[av * 4 + 1][ar] = a4.y;
        As[av * 4 + 2][ar] = a4.z;
        As[av * 4 + 3][ar] = a4.w;
        *(float4*)(&Bs[br][bv * 4]) = *(const float4*)(Bptr + (size_t)kt * NH);
        __syncthreads();
        #pragma unroll
        for (int k = 0; k < BK; k++) {
            float4 a = *(const float4*)(&As[k][ty * 4]);
            float4 b = *(const float4*)(&Bs[k][tx * 4]);
            acc[0][0] += a.x * b.x; acc[0][1] += a.x * b.y; acc[0][2] += a.x * b.z; acc[0][3] += a.x * b.w;
            acc[1][0] += a.y * b.x; acc[1][1] += a.y * b.y; acc[1][2] += a.y * b.z; acc[1][3] += a.y * b.w;
            acc[2][0] += a.z * b.x; acc[2][1] += a.z * b.y; acc[2][2] += a.z * b.z; acc[2][3] += a.z * b.w;
            acc[3][0] += a.w * b.x; acc[3][1] += a.w * b.y; acc[3][2] += a.w * b.z; acc[3][3] += a.w * b.w;
        }
        __syncthreads();
    }

    float* X = g_x + (size_t)(m0 + ty * 4) * NH + n0 + tx * 4;
    #pragma unroll
    for (int r = 0; r < 4; r++) {
        float4 o = make_float4(acc[r][0], acc[r][1], acc[r][2], acc[r][3]);
        *(float4*)(X + (size_t)r * NH) = o;
    }
}

// ---------------- 4) per-node attention scalars ------------------------------
__global__ void k_attvec(const float* __restrict__ att_src,
                         const float* __restrict__ att_dst) {
    int n = blockIdx.x;
    int h = threadIdx.x >> 5, lane = threadIdx.x & 31;  // 4 warps, one per head
    const float* xr = g_x + (size_t)n * NH + h * EMB;
    const float* as = att_src + h * EMB;
    const float* ad = att_dst + h * EMB;
    float s1 = 0.f, s2 = 0.f;
    for (int e = lane; e < EMB; e += 32) {
        float v = xr[e];
        s1 += v * as[e];
        s2 += v * ad[e];
    }
    #pragma unroll
    for (int o = 16; o > 0; o >>= 1) {
        s1 += __shfl_down_sync(0xffffffffu, s1, o);
        s2 += __shfl_down_sync(0xffffffffu, s2, o);
    }
    if (lane == 0) {
        g_asrc[n * HEADS + h] = s1;
        g_adst[n * HEADS + h] = s2;
    }
}

// ---------------- 5) band softmax + weighted aggregation ---------------------
__global__ void k_attn(const float* __restrict__ bias, float* __restrict__ out) {
    int i = blockIdx.x;
    __shared__ float alpha[HEADS][BW + 1];  // logits first, then alphas
    unsigned m = g_mask[i];
    int t = threadIdx.x;

    if (t < HEADS * BW) {
        int h = t / BW, d = t % BW;
        int j = i - BAND + d;
        float l = -INFINITY;
        if (j >= 0 && j < N_SPANS && ((m >> d) & 1u)) {
            float v = g_adst[i * HEADS + h] + g_asrc[j * HEADS + h];
            l = (v >= 0.f) ? v : 0.2f * v;
        }
        alpha[h][d] = l;
    }
    __syncthreads();

    if (t < HEADS) {
        float mx = -INFINITY;
        #pragma unroll
        for (int d = 0; d < BW; d++) mx = fmaxf(mx, alpha[t][d]);
        float ex[BW];
        float s = 0.f;
        #pragma unroll
        for (int d = 0; d < BW; d++) { float e = expf(alpha[t][d] - mx); ex[d] = e; s += e; }
        float inv = 1.f / s;
        #pragma unroll
        for (int d = 0; d < BW; d++) alpha[t][d] = ex[d] * inv;
    }
    __syncthreads();

    int jlo = (i - BAND < 0) ? 0 : i - BAND;
    int jhi = (i + BAND >= N_SPANS) ? N_SPANS - 1 : i + BAND;

    for (int e = t; e < EMB; e += 128) {
        float acc = 0.f;
        for (int j = jlo; j <= jhi; j++) {
            int d = j - (i - BAND);
            const float* xr = g_x + (size_t)j * NH + e;
            acc += alpha[0][d] * xr[0]
                 + alpha[1][d] * xr[EMB]
                 + alpha[2][d] * xr[2 * EMB]
                 + alpha[3][d] * xr[3 * EMB];
        }
        out[i * EMB + e] = acc * 0.25f + bias[e];
    }
}

// -----------------------------------------------------------------------------
extern "C" void kernel_launch(void* const* d_in, const int* in_sizes, int n_in,
                              void* d_out, int out_size) {
    const float* E    = (const float*)d_in[0];
    // d_in[1] = span_positions (int64) — unused by the reference
    const float* W    = (const float*)d_in[2];   // [384, 4, 384] == [384, 1536] row-major
    const float* asv  = (const float*)d_in[3];   // att_src [4, 384]
    const float* adv  = (const float*)d_in[4];   // att_dst [4, 384]
    const float* bias = (const float*)d_in[5];   // [384]
    float* out = (float*)d_out;                  // [4096, 384] fp32

    k_norm<<<N_SPANS, 128>>>(E);
    k_mask<<<N_SPANS, 256>>>();
    k_gemm<<<dim3(NH / BN, N_SPANS / BM), 256>>>(E, W);
    k_attvec<<<N_SPANS, 128>>>(asv, adv);
    k_attn<<<N_SPANS, 128>>>(bias, out);
}